// round 9
// baseline (speedup 1.0000x reference)
#include <cuda_runtime.h>
#include <cuda_fp16.h>

#define T_DIM 200
#define B_DIM 64
#define E_DIM 64
#define NROWS (T_DIM * B_DIM)   // 12800
#define BH (B_DIM * E_DIM)      // 4096
#define LOG2E 1.4426950408889634f

// ---- scratch ----
__device__ __half2 g_x1h[NROWS * 32];   // x1 pre-scaled by 0.5, half2 packed
__device__ float   g_y2[NROWS * E_DIM];
__device__ float   g_y3[NROWS * E_DIM];
__device__ __half  g_qh[NROWS * E_DIM]; // q pre-scaled by 0.5, half
__device__ float   g_ma[NROWS * E_DIM];
__device__ float   g_t0[4 * NROWS * 64];

__constant__ int c_IBB[16] = {0,1,2,2,3,3,4,4,4,5,5,5,6,6,6,6};
__constant__ int c_JC [16] = {0,0,0,1,0,1,0,1,2,0,1,2,0,1,2,3};

__device__ __forceinline__ float ex2f(float x) {
    float r; asm("ex2.approx.f32 %0, %1;" : "=f"(r) : "f"(x)); return r;
}
__device__ __forceinline__ float rcpf(float x) {
    float r; asm("rcp.approx.f32 %0, %1;" : "=f"(r) : "f"(x)); return r;
}
__device__ __forceinline__ float sigf(float v) {
    return rcpf(1.0f + ex2f(-v * LOG2E));
}
__device__ __forceinline__ float leakyf(float v) {
    return (v >= 0.0f) ? v : 0.3f * v;
}
// ---- f16x2 helpers ----
__device__ __forceinline__ unsigned tanh2u(unsigned x) {
    unsigned r; asm("tanh.approx.f16x2 %0, %1;" : "=r"(r) : "r"(x)); return r;
}
__device__ __forceinline__ unsigned hadd2u(unsigned a, unsigned b) {
    unsigned r; asm("add.f16x2 %0, %1, %2;" : "=r"(r) : "r"(a), "r"(b)); return r;
}
__device__ __forceinline__ unsigned hfma2u(unsigned a, unsigned b, unsigned c) {
    unsigned r; asm("fma.rn.f16x2 %0, %1, %2, %3;" : "=r"(r) : "r"(a), "r"(b), "r"(c)); return r;
}
__device__ __forceinline__ unsigned f2h2(float hi, float lo) {   // pack {lo, hi}
    unsigned r; asm("cvt.rn.f16x2.f32 %0, %1, %2;" : "=r"(r) : "f"(hi), "f"(lo)); return r;
}
__device__ __forceinline__ float2 h22f2(unsigned u) {
    float2 f;
    asm("{ .reg .f16 l, h; mov.b32 {l, h}, %2; cvt.f32.f16 %0, l; cvt.f32.f16 %1, h; }"
        : "=f"(f.x), "=f"(f.y) : "r"(u));
    return f;
}
// ---- f32x2 helpers ----
__device__ __forceinline__ unsigned long long pk2(float v) {
    unsigned long long r; asm("mov.b64 %0, {%1, %1};" : "=l"(r) : "f"(v)); return r;
}
__device__ __forceinline__ void ffma2(unsigned long long& d,
                                      unsigned long long a, unsigned long long b) {
    asm("fma.rn.f32x2 %0, %1, %2, %0;" : "+l"(d) : "l"(a), "l"(b));
}
__device__ __forceinline__ float2 up2(unsigned long long v) {
    float2 f; asm("mov.b64 {%0, %1}, %2;" : "=f"(f.x), "=f"(f.y) : "l"(v)); return f;
}

// ============================================================================
// GEMM (HOUT=64), up to 5 towers, f32x2 inner.
// act: 0=none, 1=leaky, 2 = *0.5 then convert to half2 (Y is __half2*)
// ============================================================================
struct GemmBatch {
    const float* X[5];
    const float* W[5];
    const float* B[5];
    float*       Y[5];
    int          act[5];
};

__global__ void __launch_bounds__(256) gemm64_k(GemmBatch gb)
{
    constexpr int ROWS = 128;
    __shared__ __align__(16) float Xt[64][ROWS + 4];
    __shared__ __align__(16) float Ws[64][64];
    __shared__ float Bs[64];

    const int tw = blockIdx.y;
    const float* __restrict__ X  = gb.X[tw];
    const float* __restrict__ W  = gb.W[tw];
    const float* __restrict__ Bp = gb.B[tw];
    float* __restrict__ Y        = gb.Y[tw];
    const int act = gb.act[tw];

    const int tid = threadIdx.x;
    const int r0  = blockIdx.x * ROWS;

    for (int idx = tid; idx < 64 * 64; idx += 256)
        Ws[idx >> 6][idx & 63] = W[idx];
    if (tid < 64) Bs[tid] = Bp ? Bp[tid] : 0.0f;
    for (int idx = tid; idx < ROWS * 16; idx += 256) {
        int r  = idx & 127;
        int k4 = (idx >> 7) << 2;
        float4 v = *(const float4*)&X[(size_t)(r0 + r) * 64 + k4];
        Xt[k4 + 0][r] = v.x; Xt[k4 + 1][r] = v.y;
        Xt[k4 + 2][r] = v.z; Xt[k4 + 3][r] = v.w;
    }
    __syncthreads();

    const int tc = tid & 15;
    const int tr = tid >> 4;
    unsigned long long acc[4][4];    // [row-pair][col], f32x2
    #pragma unroll
    for (int p = 0; p < 4; p++)
        #pragma unroll
        for (int c = 0; c < 4; c++) acc[p][c] = 0ull;

    #pragma unroll 8
    for (int k = 0; k < 64; k++) {
        ulonglong2 X0 = *(const ulonglong2*)&Xt[k][tr * 8];
        ulonglong2 X1 = *(const ulonglong2*)&Xt[k][tr * 8 + 4];
        float4 wv = *(const float4*)&Ws[k][tc * 4];
        unsigned long long wp[4] = {pk2(wv.x), pk2(wv.y), pk2(wv.z), pk2(wv.w)};
        #pragma unroll
        for (int c = 0; c < 4; c++) {
            ffma2(acc[0][c], X0.x, wp[c]);
            ffma2(acc[1][c], X0.y, wp[c]);
            ffma2(acc[2][c], X1.x, wp[c]);
            ffma2(acc[3][c], X1.y, wp[c]);
        }
    }

    #pragma unroll
    for (int p = 0; p < 4; p++) {
        float r0c[4], r1c[4];
        #pragma unroll
        for (int c = 0; c < 4; c++) {
            float2 f = up2(acc[p][c]);
            r0c[c] = f.x + Bs[tc * 4 + c];
            r1c[c] = f.y + Bs[tc * 4 + c];
        }
        int rowa = r0 + tr * 8 + 2 * p;
        if (act == 2) {
            __half2* Yh = (__half2*)Y;
            uint2 o0, o1;
            o0.x = f2h2(r0c[1] * 0.5f, r0c[0] * 0.5f);
            o0.y = f2h2(r0c[3] * 0.5f, r0c[2] * 0.5f);
            o1.x = f2h2(r1c[1] * 0.5f, r1c[0] * 0.5f);
            o1.y = f2h2(r1c[3] * 0.5f, r1c[2] * 0.5f);
            *(uint2*)&Yh[(size_t)rowa * 32 + tc * 2]       = o0;
            *(uint2*)&Yh[(size_t)(rowa + 1) * 32 + tc * 2] = o1;
        } else {
            float4 o0, o1;
            if (act == 1) {
                o0 = make_float4(leakyf(r0c[0]), leakyf(r0c[1]), leakyf(r0c[2]), leakyf(r0c[3]));
                o1 = make_float4(leakyf(r1c[0]), leakyf(r1c[1]), leakyf(r1c[2]), leakyf(r1c[3]));
            } else {
                o0 = make_float4(r0c[0], r0c[1], r0c[2], r0c[3]);
                o1 = make_float4(r1c[0], r1c[1], r1c[2], r1c[3]);
            }
            *(float4*)&Y[(size_t)rowa * 64 + tc * 4]       = o0;
            *(float4*)&Y[(size_t)(rowa + 1) * 64 + tc * 4] = o1;
        }
    }
}

// ============================================================================
// merged scan (+ zero g_ma): 128 blocks x 256 thr. Block = 32 columns.
// Warp w handles t in [w*25, w*25+25). Cross-segment prefix via smem.
// ============================================================================
__global__ void __launch_bounds__(256) scan_k()
{
    __shared__ float parts[8][32];

    const int tid  = blockIdx.x * 256 + threadIdx.x;
    // zero g_ma: 204800 float4 / 32768 threads = 6.25
    {
        float4 z4 = make_float4(0.f, 0.f, 0.f, 0.f);
        float4* mz = (float4*)g_ma;
        for (int i = tid; i < NROWS * 16; i += 32768) mz[i] = z4;
    }

    const int lane = threadIdx.x & 31;
    const int w    = threadIdx.x >> 5;        // segment 0..7
    const int col  = blockIdx.x * 32 + lane;
    const int t0   = w * 25;

    float s = 0.0f;
    #pragma unroll
    for (int t = 0; t < 25; t++)
        s += g_y3[(size_t)(t0 + t) * BH + col];
    parts[w][lane] = s;
    __syncthreads();

    float acc = 0.0f;
    #pragma unroll
    for (int p = 0; p < 7; p++) {
        float v = parts[p][lane];
        if (p < w) acc += v;
    }

    #pragma unroll
    for (int t = 0; t < 25; t++) {
        size_t o = (size_t)(t0 + t) * BH + col;
        acc += g_y3[o];
        float invt = __fdividef(1.0f, (float)(t0 + t + 1));
        g_qh[o] = __float2half((g_y2[o] + acc * invt) * 0.5f);
    }
}

// ============================================================================
// attention: grid (16, 64). Block = 32 i x (1-2 tiles of 32 j).
// Score phase: warp wid -> i's iw..iw+3, lane=j; uint4 f16x2 datapath.
// Rank-1 phase: transposed scores; warp wid -> h slice [8w,8w+8), lane=i.
// ============================================================================
__global__ void __launch_bounds__(256) attn_k(const float* __restrict__ inp,
                                              const float* __restrict__ w0)
{
    __shared__ __align__(16) unsigned x1s[32 * 36];   // half2, row stride 36
    __shared__ __align__(16) unsigned qhs[32 * 36];   // half2, row stride 36
    __shared__ __align__(16) unsigned w0h[32];        // half2 pairs of w0
    __shared__ __align__(16) float    w0f[64];
    __shared__ __align__(16) float    insp[32][68];   // inp tile, fp32
    __shared__ __align__(4)  float    sstT[32][33];   // [j][i_local]

    const int b    = blockIdx.y;
    const int ibb  = c_IBB[blockIdx.x];
    const int jc   = c_JC[blockIdx.x];
    const int i0   = ibb * 32;
    const int tid  = threadIdx.x;
    const int wid  = tid >> 5;
    const int lane = tid & 31;
    const int iw   = wid << 2;

    if (tid < 64) w0f[tid] = w0[tid];
    if (tid >= 64 && tid < 96) {
        int t = tid - 64;
        w0h[t] = f2h2(w0[2 * t + 1], w0[2 * t]);
    }
    {   // q tile: 32 rows x 8 uint4 (each uint4 = 8 halfs)
        int r = tid >> 3, c = tid & 7;
        int ii = i0 + r;
        uint4 v = make_uint4(0u, 0u, 0u, 0u);
        if (ii < T_DIM)
            v = ((const uint4*)(g_qh + (size_t)ii * BH + b * 64))[c];
        *(uint4*)&qhs[r * 36 + c * 4] = v;
    }
    __syncthreads();

    float hw0 = 0.0f;
    #pragma unroll 16
    for (int h = 0; h < 64; h++) hw0 += w0f[h];
    hw0 *= 0.5f;

    float macc[8];
    #pragma unroll
    for (int k = 0; k < 8; k++) macc[k] = 0.0f;

    const int ntiles = (2 * jc + 1 <= ibb) ? 2 : 1;

    for (int t = 0; t < ntiles; t++) {
        const int j0 = (2 * jc + t) * 32;
        if (t) __syncthreads();
        {   // x1 tile (half2): 32 rows x 8 uint4
            int jj = tid >> 3, c = tid & 7;
            int j = j0 + jj;
            uint4 v = make_uint4(0u, 0u, 0u, 0u);
            if (j < T_DIM)
                v = ((const uint4*)(g_x1h + ((size_t)j * B_DIM + b) * 32))[c];
            *(uint4*)&x1s[jj * 36 + c * 4] = v;
        }
        {   // inp tile (fp32): 32 rows x 8 chunks of 8 floats
            int jj = tid >> 3;
            int h8 = (tid & 7) << 3;
            int j = j0 + jj;
            float4 va = make_float4(0.f, 0.f, 0.f, 0.f), vb = va;
            if (j < T_DIM) {
                const float* pi = &inp[(size_t)j * BH + b * 64 + h8];
                va = *(const float4*)pi;
                vb = *(const float4*)(pi + 4);
            }
            *(float4*)&insp[jj][h8]     = va;
            *(float4*)&insp[jj][h8 + 4] = vb;
        }
        __syncthreads();

        // ---- score phase ----
        unsigned a0[4], a1[4];
        #pragma unroll
        for (int k = 0; k < 4; k++) { a0[k] = 0u; a1[k] = 0u; }

        const unsigned* xr = &x1s[lane * 36];
        #pragma unroll
        for (int c = 0; c < 8; c++) {
            uint4 xv = *(const uint4*)&xr[c * 4];
            uint4 wv = *(const uint4*)&w0h[c * 4];
            uint4 q0 = *(const uint4*)&qhs[(iw + 0) * 36 + c * 4];
            uint4 q1 = *(const uint4*)&qhs[(iw + 1) * 36 + c * 4];
            uint4 q2 = *(const uint4*)&qhs[(iw + 2) * 36 + c * 4];
            uint4 q3 = *(const uint4*)&qhs[(iw + 3) * 36 + c * 4];
            a0[0] = hfma2u(wv.x, tanh2u(hadd2u(xv.x, q0.x)), a0[0]);
            a0[1] = hfma2u(wv.x, tanh2u(hadd2u(xv.x, q1.x)), a0[1]);
            a0[2] = hfma2u(wv.x, tanh2u(hadd2u(xv.x, q2.x)), a0[2]);
            a0[3] = hfma2u(wv.x, tanh2u(hadd2u(xv.x, q3.x)), a0[3]);
            a1[0] = hfma2u(wv.y, tanh2u(hadd2u(xv.y, q0.y)), a1[0]);
            a1[1] = hfma2u(wv.y, tanh2u(hadd2u(xv.y, q1.y)), a1[1]);
            a1[2] = hfma2u(wv.y, tanh2u(hadd2u(xv.y, q2.y)), a1[2]);
            a1[3] = hfma2u(wv.y, tanh2u(hadd2u(xv.y, q3.y)), a1[3]);
            a0[0] = hfma2u(wv.z, tanh2u(hadd2u(xv.z, q0.z)), a0[0]);
            a0[1] = hfma2u(wv.z, tanh2u(hadd2u(xv.z, q1.z)), a0[1]);
            a0[2] = hfma2u(wv.z, tanh2u(hadd2u(xv.z, q2.z)), a0[2]);
            a0[3] = hfma2u(wv.z, tanh2u(hadd2u(xv.z, q3.z)), a0[3]);
            a1[0] = hfma2u(wv.w, tanh2u(hadd2u(xv.w, q0.w)), a1[0]);
            a1[1] = hfma2u(wv.w, tanh2u(hadd2u(xv.w, q1.w)), a1[1]);
            a1[2] = hfma2u(wv.w, tanh2u(hadd2u(xv.w, q2.w)), a1[2]);
            a1[3] = hfma2u(wv.w, tanh2u(hadd2u(xv.w, q3.w)), a1[3]);
        }

        const int j   = j0 + lane;
        const int ib2 = i0 + iw;
        #pragma unroll
        for (int k = 0; k < 4; k++) {
            float2 fa = h22f2(a0[k]);
            float2 fb = h22f2(a1[k]);
            float d = (fa.x + fa.y) + (fb.x + fb.y);
            sstT[lane][iw + k] =
                (j <= ib2 + k && j < T_DIM) ? fmaf(0.5f, d, hw0) : 0.0f;
        }
        __syncthreads();

        // ---- rank-1 phase: warp wid -> h slice, lane -> i ----
        const int h0 = wid << 3;
        #pragma unroll 8
        for (int jj = 0; jj < 32; jj++) {
            float sc = sstT[jj][lane];                    // conflict-free LDS.32
            float4 v0 = *(const float4*)&insp[jj][h0];    // broadcast
            float4 v1 = *(const float4*)&insp[jj][h0 + 4];
            macc[0] += sc * v0.x; macc[1] += sc * v0.y;
            macc[2] += sc * v0.z; macc[3] += sc * v0.w;
            macc[4] += sc * v1.x; macc[5] += sc * v1.y;
            macc[6] += sc * v1.z; macc[7] += sc * v1.w;
        }
    }

    const int i = i0 + lane;
    if (i < T_DIM) {
        float* dst = &g_ma[(size_t)i * BH + b * 64 + (wid << 3)];
        #pragma unroll
        for (int k = 0; k < 8; k++) atomicAdd(dst + k, macc[k]);
    }
}

// ============================================================================
// fused L1 + final (64-row tiles -> 200 blocks)
// ============================================================================
struct L1FArgs {
    const float* W[4];
    const float* B[4];
};

__global__ void __launch_bounds__(256) l1f_k(L1FArgs la, float* __restrict__ out)
{
    constexpr int ROWS = 64;
    __shared__ float Xa[64][ROWS + 4];
    __shared__ float Xb[64][ROWS + 4];
    __shared__ float Wa[64][32];
    __shared__ float Wb[64][32];
    __shared__ float Ba[32], Bb[32];

    const int tid = threadIdx.x;
    const int r0  = blockIdx.x * ROWS;
    const int tc  = tid & 7;
    const int tr  = tid >> 3;

    float pcv[2];
    float res[2][2];

    #pragma unroll
    for (int p = 0; p < 2; p++) {
        const float* Ta = g_t0 + (size_t)(2 * p)     * NROWS * 64;
        const float* Tb = g_t0 + (size_t)(2 * p + 1) * NROWS * 64;

        __syncthreads();
        for (int idx = tid; idx < ROWS * 16; idx += 256) {
            int r  = idx & 63;
            int k4 = (idx >> 6) << 2;
            float4 va = *(const float4*)&Ta[(size_t)(r0 + r) * 64 + k4];
            float4 vb = *(const float4*)&Tb[(size_t)(r0 + r) * 64 + k4];
            Xa[k4 + 0][r] = va.x; Xa[k4 + 1][r] = va.y;
            Xa[k4 + 2][r] = va.z; Xa[k4 + 3][r] = va.w;
            Xb[k4 + 0][r] = vb.x; Xb[k4 + 1][r] = vb.y;
            Xb[k4 + 2][r] = vb.z; Xb[k4 + 3][r] = vb.w;
        }
        for (int idx = tid; idx < 64 * 32; idx += 256) {
            Wa[idx >> 5][idx & 31] = la.W[2 * p][idx];
            Wb[idx >> 5][idx & 31] = la.W[2 * p + 1][idx];
        }
        if (tid < 32) { Ba[tid] = la.B[2 * p][tid]; Bb[tid] = la.B[2 * p + 1][tid]; }
        __syncthreads();

        float aa[2][4], ab[2][4];
        #pragma unroll
        for (int a = 0; a < 2; a++)
            #pragma unroll
            for (int c = 0; c < 4; c++) { aa[a][c] = 0.0f; ab[a][c] = 0.0f; }

        #pragma unroll 8
        for (int k = 0; k < 64; k++) {
            float2 xa = *(const float2*)&Xa[k][tr * 2];
            float2 xb = *(const float2*)&Xb[k][tr * 2];
            float4 wa = *(const float4*)&Wa[k][tc * 4];
            float4 wb = *(const float4*)&Wb[k][tc * 4];
            float xar[2] = {xa.x, xa.y};
            float xbr[2] = {xb.x, xb.y};
            float war[4] = {wa.x, wa.y, wa.z, wa.w};
            float wbr[4] = {wb.x, wb.y, wb.z, wb.w};
            #pragma unroll
            for (int a = 0; a < 2; a++)
                #pragma unroll
                for (int c = 0; c < 4; c++) {
                    aa[a][c] += xar[a] * war[c];
                    ab[a][c] += xbr[a] * wbr[c];
                }
        }

        #pragma unroll
        for (int a = 0; a < 2; a++) {
            float z = 0.0f;
            #pragma unroll
            for (int c = 0; c < 4; c++) {
                float va = leakyf(aa[a][c] + Ba[tc * 4 + c]);
                float vb = leakyf(ab[a][c] + Bb[tc * 4 + c]);
                z += va * vb;
            }
            #pragma unroll
            for (int off = 1; off < 8; off <<= 1)
                z += __shfl_xor_sync(0xffffffffu, z, off);
            res[p][a] = z;
        }
        if (p == 0) {
            #pragma unroll
            for (int a = 0; a < 2; a++) pcv[a] = sigf(res[0][a]);
        }
    }

    if (tc == 0) {
        #pragma unroll
        for (int a = 0; a < 2; a++) {
            int row = r0 + tr * 2 + a;
            float pc = pcv[a];
            float pv = sigf(res[1][a]) * pc;
            out[row]         = pc;
            out[NROWS + row] = pv;
        }
    }
}

// ============================================================================
extern "C" void kernel_launch(void* const* d_in, const int* in_sizes, int n_in,
                              void* d_out, int out_size)
{
    (void)in_sizes; (void)n_in; (void)out_size;
    const float* inp     = (const float*)d_in[0];
    const float* w1k     = (const float*)d_in[1];
    const float* w1b     = (const float*)d_in[2];
    const float* w2k     = (const float*)d_in[3];
    const float* w3k     = (const float*)d_in[4];
    const float* w0k     = (const float*)d_in[5];
    const float* pc_a0_k = (const float*)d_in[6],  *pc_a0_b = (const float*)d_in[7];
    const float* pc_b0_k = (const float*)d_in[8],  *pc_b0_b = (const float*)d_in[9];
    const float* pc_a1_k = (const float*)d_in[10], *pc_a1_b = (const float*)d_in[11];
    const float* pc_b1_k = (const float*)d_in[12], *pc_b1_b = (const float*)d_in[13];
    const float* pv_a0_k = (const float*)d_in[14], *pv_a0_b = (const float*)d_in[15];
    const float* pv_b0_k = (const float*)d_in[16], *pv_b0_b = (const float*)d_in[17];
    const float* pv_a1_k = (const float*)d_in[18], *pv_a1_b = (const float*)d_in[19];
    const float* pv_b1_k = (const float*)d_in[20], *pv_b1_b = (const float*)d_in[21];

    float *x1h, *y2, *y3, *ma, *t0;
    cudaGetSymbolAddress((void**)&x1h, g_x1h);
    cudaGetSymbolAddress((void**)&y2, g_y2);
    cudaGetSymbolAddress((void**)&y3, g_y3);
    cudaGetSymbolAddress((void**)&ma, g_ma);
    cudaGetSymbolAddress((void**)&t0, g_t0);

    // 1) x1 (-> half2, *0.5), y2, y3, + inp-only L0 towers (pc_b0, pv_b0)
    GemmBatch A = {};
    A.X[0] = inp; A.W[0] = w1k;     A.B[0] = w1b;     A.Y[0] = x1h;                          A.act[0] = 2;
    A.X[1] = inp; A.W[1] = w2k;     A.B[1] = nullptr; A.Y[1] = y2;                           A.act[1] = 0;
    A.X[2] = inp; A.W[2] = w3k;     A.B[2] = nullptr; A.Y[2] = y3;                           A.act[2] = 0;
    A.X[3] = inp; A.W[3] = pc_b0_k; A.B[3] = pc_b0_b; A.Y[3] = t0 + 1 * (size_t)NROWS * 64;  A.act[3] = 1;
    A.X[4] = inp; A.W[4] = pv_b0_k; A.B[4] = pv_b0_b; A.Y[4] = t0 + 3 * (size_t)NROWS * 64;  A.act[4] = 1;
    gemm64_k<<<dim3(NROWS / 128, 5), 256>>>(A);

    // 2) merged scan (also zeroes g_ma); emits q in half
    scan_k<<<BH / 32, 256>>>();

    // 3) scores + m_a (f16x2 tanh, h-sliced rank-1, atomic accumulate)
    attn_k<<<dim3(16, B_DIM), 256>>>(inp, w0k);

    // 4) ma-based L0 towers
    GemmBatch L0 = {};
    L0.X[0] = ma; L0.W[0] = pc_a0_k; L0.B[0] = pc_a0_b; L0.Y[0] = t0 + 0 * (size_t)NROWS * 64; L0.act[0] = 1;
    L0.X[1] = ma; L0.W[1] = pv_a0_k; L0.B[1] = pv_a0_b; L0.Y[1] = t0 + 2 * (size_t)NROWS * 64; L0.act[1] = 1;
    gemm64_k<<<dim3(NROWS / 128, 2), 256>>>(L0);

    // 5) fused L1 + product-reduce + sigmoid
    L1FArgs la = {};
    la.W[0] = pc_a1_k; la.B[0] = pc_a1_b;
    la.W[1] = pc_b1_k; la.B[1] = pc_b1_b;
    la.W[2] = pv_a1_k; la.B[2] = pv_a1_b;
    la.W[3] = pv_b1_k; la.B[3] = pv_b1_b;
    l1f_k<<<NROWS / 64, 256>>>(la, (float*)d_out);
}

// round 10
// speedup vs baseline: 1.0930x; 1.0930x over previous
#include <cuda_runtime.h>
#include <cuda_fp16.h>

#define T_DIM 200
#define B_DIM 64
#define E_DIM 64
#define NROWS (T_DIM * B_DIM)   // 12800
#define BH (B_DIM * E_DIM)      // 4096
#define LOG2E 1.4426950408889634f

// ---- scratch ----
__device__ __half2 g_x1h[NROWS * 32];   // x1 pre-scaled by 0.5, half2 packed
__device__ float   g_y2[NROWS * E_DIM];
__device__ float   g_y3[NROWS * E_DIM];
__device__ __half  g_qh[NROWS * E_DIM]; // q pre-scaled by 0.5, half
__device__ float   g_ma[NROWS * E_DIM];
__device__ float   g_t0[4 * NROWS * 64];

__constant__ int c_IBB[16] = {0,1,2,2,3,3,4,4,4,5,5,5,6,6,6,6};
__constant__ int c_JC [16] = {0,0,0,1,0,1,0,1,2,0,1,2,0,1,2,3};

__device__ __forceinline__ float ex2f(float x) {
    float r; asm("ex2.approx.f32 %0, %1;" : "=f"(r) : "f"(x)); return r;
}
__device__ __forceinline__ float rcpf(float x) {
    float r; asm("rcp.approx.f32 %0, %1;" : "=f"(r) : "f"(x)); return r;
}
__device__ __forceinline__ float sigf(float v) {
    return rcpf(1.0f + ex2f(-v * LOG2E));
}
__device__ __forceinline__ float leakyf(float v) {
    return (v >= 0.0f) ? v : 0.3f * v;
}
// ---- f16x2 helpers ----
__device__ __forceinline__ unsigned tanh2u(unsigned x) {
    unsigned r; asm("tanh.approx.f16x2 %0, %1;" : "=r"(r) : "r"(x)); return r;
}
__device__ __forceinline__ unsigned hadd2u(unsigned a, unsigned b) {
    unsigned r; asm("add.f16x2 %0, %1, %2;" : "=r"(r) : "r"(a), "r"(b)); return r;
}
__device__ __forceinline__ unsigned hfma2u(unsigned a, unsigned b, unsigned c) {
    unsigned r; asm("fma.rn.f16x2 %0, %1, %2, %3;" : "=r"(r) : "r"(a), "r"(b), "r"(c)); return r;
}
__device__ __forceinline__ unsigned f2h2(float hi, float lo) {
    unsigned r; asm("cvt.rn.f16x2.f32 %0, %1, %2;" : "=r"(r) : "f"(hi), "f"(lo)); return r;
}
__device__ __forceinline__ float2 h22f2(unsigned u) {
    float2 f;
    asm("{ .reg .f16 l, h; mov.b32 {l, h}, %2; cvt.f32.f16 %0, l; cvt.f32.f16 %1, h; }"
        : "=f"(f.x), "=f"(f.y) : "r"(u));
    return f;
}
// ---- f32x2 helpers ----
__device__ __forceinline__ unsigned long long pk2(float v) {
    unsigned long long r; asm("mov.b64 %0, {%1, %1};" : "=l"(r) : "f"(v)); return r;
}
__device__ __forceinline__ void ffma2(unsigned long long& d,
                                      unsigned long long a, unsigned long long b) {
    asm("fma.rn.f32x2 %0, %1, %2, %0;" : "+l"(d) : "l"(a), "l"(b));
}
__device__ __forceinline__ float2 up2(unsigned long long v) {
    float2 f; asm("mov.b64 {%0, %1}, %2;" : "=f"(f.x), "=f"(f.y) : "l"(v)); return f;
}

// ============================================================================
// GEMM (HOUT=64), up to 5 towers, f32x2 inner, 64-row tiles (34KB smem).
// act: 0=none, 1=leaky, 2 = *0.5 then convert to half2 (Y is __half2*)
// ============================================================================
struct GemmBatch {
    const float* X[5];
    const float* W[5];
    const float* B[5];
    float*       Y[5];
    int          act[5];
};

__global__ void __launch_bounds__(256) gemm64_k(GemmBatch gb)
{
    constexpr int ROWS = 64;
    __shared__ __align__(16) float Xt[64][ROWS + 4];
    __shared__ __align__(16) float Ws[64][64];
    __shared__ float Bs[64];

    const int tw = blockIdx.y;
    const float* __restrict__ X  = gb.X[tw];
    const float* __restrict__ W  = gb.W[tw];
    const float* __restrict__ Bp = gb.B[tw];
    float* __restrict__ Y        = gb.Y[tw];
    const int act = gb.act[tw];

    const int tid = threadIdx.x;
    const int r0  = blockIdx.x * ROWS;

    for (int idx = tid; idx < 64 * 64; idx += 256)
        Ws[idx >> 6][idx & 63] = W[idx];
    if (tid < 64) Bs[tid] = Bp ? Bp[tid] : 0.0f;
    for (int idx = tid; idx < ROWS * 16; idx += 256) {
        int r  = idx & 63;
        int k4 = (idx >> 6) << 2;
        float4 v = *(const float4*)&X[(size_t)(r0 + r) * 64 + k4];
        Xt[k4 + 0][r] = v.x; Xt[k4 + 1][r] = v.y;
        Xt[k4 + 2][r] = v.z; Xt[k4 + 3][r] = v.w;
    }
    __syncthreads();

    const int tc = tid & 15;        // 16 col-groups * 4 cols
    const int tr = tid >> 4;        // 16 row-groups * 4 rows
    unsigned long long acc[2][4];   // [row-pair][col], f32x2
    #pragma unroll
    for (int p = 0; p < 2; p++)
        #pragma unroll
        for (int c = 0; c < 4; c++) acc[p][c] = 0ull;

    #pragma unroll 8
    for (int k = 0; k < 64; k++) {
        ulonglong2 X0 = *(const ulonglong2*)&Xt[k][tr * 4];   // 4 rows = 2 f32x2
        float4 wv = *(const float4*)&Ws[k][tc * 4];
        unsigned long long wp[4] = {pk2(wv.x), pk2(wv.y), pk2(wv.z), pk2(wv.w)};
        #pragma unroll
        for (int c = 0; c < 4; c++) {
            ffma2(acc[0][c], X0.x, wp[c]);
            ffma2(acc[1][c], X0.y, wp[c]);
        }
    }

    #pragma unroll
    for (int p = 0; p < 2; p++) {
        float r0c[4], r1c[4];
        #pragma unroll
        for (int c = 0; c < 4; c++) {
            float2 f = up2(acc[p][c]);
            r0c[c] = f.x + Bs[tc * 4 + c];
            r1c[c] = f.y + Bs[tc * 4 + c];
        }
        int rowa = r0 + tr * 4 + 2 * p;
        if (act == 2) {
            __half2* Yh = (__half2*)Y;
            uint2 o0, o1;
            o0.x = f2h2(r0c[1] * 0.5f, r0c[0] * 0.5f);
            o0.y = f2h2(r0c[3] * 0.5f, r0c[2] * 0.5f);
            o1.x = f2h2(r1c[1] * 0.5f, r1c[0] * 0.5f);
            o1.y = f2h2(r1c[3] * 0.5f, r1c[2] * 0.5f);
            *(uint2*)&Yh[(size_t)rowa * 32 + tc * 2]       = o0;
            *(uint2*)&Yh[(size_t)(rowa + 1) * 32 + tc * 2] = o1;
        } else {
            float4 o0, o1;
            if (act == 1) {
                o0 = make_float4(leakyf(r0c[0]), leakyf(r0c[1]), leakyf(r0c[2]), leakyf(r0c[3]));
                o1 = make_float4(leakyf(r1c[0]), leakyf(r1c[1]), leakyf(r1c[2]), leakyf(r1c[3]));
            } else {
                o0 = make_float4(r0c[0], r0c[1], r0c[2], r0c[3]);
                o1 = make_float4(r1c[0], r1c[1], r1c[2], r1c[3]);
            }
            *(float4*)&Y[(size_t)rowa * 64 + tc * 4]       = o0;
            *(float4*)&Y[(size_t)(rowa + 1) * 64 + tc * 4] = o1;
        }
    }
}

// ============================================================================
// merged scan (+ zero g_ma): 128 blocks x 256 thr. Block = 32 columns.
// ============================================================================
__global__ void __launch_bounds__(256) scan_k()
{
    __shared__ float parts[8][32];

    const int tid  = blockIdx.x * 256 + threadIdx.x;
    {
        float4 z4 = make_float4(0.f, 0.f, 0.f, 0.f);
        float4* mz = (float4*)g_ma;
        for (int i = tid; i < NROWS * 16; i += 32768) mz[i] = z4;
    }

    const int lane = threadIdx.x & 31;
    const int w    = threadIdx.x >> 5;
    const int col  = blockIdx.x * 32 + lane;
    const int t0   = w * 25;

    float s = 0.0f;
    #pragma unroll
    for (int t = 0; t < 25; t++)
        s += g_y3[(size_t)(t0 + t) * BH + col];
    parts[w][lane] = s;
    __syncthreads();

    float acc = 0.0f;
    #pragma unroll
    for (int p = 0; p < 7; p++) {
        float v = parts[p][lane];
        if (p < w) acc += v;
    }

    #pragma unroll
    for (int t = 0; t < 25; t++) {
        size_t o = (size_t)(t0 + t) * BH + col;
        acc += g_y3[o];
        float invt = __fdividef(1.0f, (float)(t0 + t + 1));
        g_qh[o] = __float2half((g_y2[o] + acc * invt) * 0.5f);
    }
}

// ============================================================================
// attention (R8 version): grid (16, 64). Block = 32 i x 64 j chunk.
// 8 warps x 4 i; f16x2 tanh; per-warp sst staging; m_a rank-1 in fp32.
// ============================================================================
__global__ void __launch_bounds__(256) attn_k(const float* __restrict__ inp,
                                              const float* __restrict__ w0)
{
    __shared__ __align__(16) unsigned x1s[32 * 34];   // half2, row stride 34
    __shared__ __align__(16) unsigned qhs[32 * 34];   // half2, row stride 34
    __shared__ __align__(16) float2   insp[32][34];   // (inp[j,h], inp[j,h+32])
    __shared__ __align__(16) unsigned w0h[32];        // half2 pairs of w0
    __shared__ __align__(16) float    w0f[64];
    __shared__ __align__(16) float4   sst[8][32];

    const int b    = blockIdx.y;
    const int ibb  = c_IBB[blockIdx.x];
    const int jc   = c_JC[blockIdx.x];
    const int i0   = ibb * 32;
    const int tid  = threadIdx.x;
    const int wid  = tid >> 5;
    const int lane = tid & 31;
    const int iw   = wid << 2;

    if (tid < 64) w0f[tid] = w0[tid];
    if (tid >= 64 && tid < 96) {
        int t = tid - 64;
        w0h[t] = f2h2(w0[2 * t + 1], w0[2 * t]);
    }
    {   // q tile: 32 rows x 8 uint4 chunks (each 4 half2)
        int r = tid >> 3, c = tid & 7;
        int ii = i0 + r;
        uint4 v = make_uint4(0u, 0u, 0u, 0u);
        if (ii < T_DIM)
            v = *(const uint4*)&g_qh[(size_t)ii * BH + b * 64 + c * 8];
        unsigned* dst = &qhs[r * 34 + c * 4];
        *(uint2*)dst       = make_uint2(v.x, v.y);
        *(uint2*)(dst + 2) = make_uint2(v.z, v.w);
    }
    __syncthreads();

    float hw0 = 0.0f;
    #pragma unroll 16
    for (int h = 0; h < 64; h++) hw0 += w0f[h];
    hw0 *= 0.5f;

    float macc[4][2];
    #pragma unroll
    for (int k = 0; k < 4; k++) { macc[k][0] = 0.0f; macc[k][1] = 0.0f; }

    const int ntiles = (2 * jc + 1 <= ibb) ? 2 : 1;

    for (int t = 0; t < ntiles; t++) {
        const int j0 = (2 * jc + t) * 32;
        if (t) __syncthreads();
        {   // x1 tile (half2): 32 rows x 8 uint4 chunks
            int jj = tid >> 3, c = tid & 7;
            int j = j0 + jj;
            uint4 v = make_uint4(0u, 0u, 0u, 0u);
            if (j < T_DIM)
                v = *(const uint4*)&g_x1h[((size_t)j * B_DIM + b) * 32 + c * 4];
            unsigned* dst = &x1s[jj * 34 + c * 4];
            *(uint2*)dst       = make_uint2(v.x, v.y);
            *(uint2*)(dst + 2) = make_uint2(v.z, v.w);
        }
        {   // inp tile (fp32 pairs)
            int jj = tid >> 3;
            int h4 = (tid & 7) << 2;
            int j = j0 + jj;
            float4 z4 = make_float4(0.f, 0.f, 0.f, 0.f);
            float4 ia = z4, ib = z4;
            if (j < T_DIM) {
                const float* pi = &inp[(size_t)j * BH + b * 64];
                ia = *(const float4*)(pi + h4);
                ib = *(const float4*)(pi + h4 + 32);
            }
            *(float4*)&insp[jj][h4]     = make_float4(ia.x, ib.x, ia.y, ib.y);
            *(float4*)&insp[jj][h4 + 2] = make_float4(ia.z, ib.z, ia.w, ib.w);
        }
        __syncthreads();

        // scores: 2 half2 chains per i
        unsigned accA[4], accB[4];
        #pragma unroll
        for (int k = 0; k < 4; k++) { accA[k] = 0u; accB[k] = 0u; }

        const unsigned* xrow = &x1s[lane * 34];
        const unsigned* q0r  = &qhs[(iw + 0) * 34];
        const unsigned* q1r  = &qhs[(iw + 1) * 34];
        const unsigned* q2r  = &qhs[(iw + 2) * 34];
        const unsigned* q3r  = &qhs[(iw + 3) * 34];

        #pragma unroll
        for (int p = 0; p < 16; p++) {
            uint2 xv = *(const uint2*)&xrow[2 * p];
            uint2 wv = *(const uint2*)&w0h[2 * p];
            uint2 q0 = *(const uint2*)&q0r[2 * p];
            uint2 q1 = *(const uint2*)&q1r[2 * p];
            uint2 q2 = *(const uint2*)&q2r[2 * p];
            uint2 q3 = *(const uint2*)&q3r[2 * p];
            accA[0] = hfma2u(wv.x, tanh2u(hadd2u(xv.x, q0.x)), accA[0]);
            accA[1] = hfma2u(wv.x, tanh2u(hadd2u(xv.x, q1.x)), accA[1]);
            accA[2] = hfma2u(wv.x, tanh2u(hadd2u(xv.x, q2.x)), accA[2]);
            accA[3] = hfma2u(wv.x, tanh2u(hadd2u(xv.x, q3.x)), accA[3]);
            accB[0] = hfma2u(wv.y, tanh2u(hadd2u(xv.y, q0.y)), accB[0]);
            accB[1] = hfma2u(wv.y, tanh2u(hadd2u(xv.y, q1.y)), accB[1]);
            accB[2] = hfma2u(wv.y, tanh2u(hadd2u(xv.y, q2.y)), accB[2]);
            accB[3] = hfma2u(wv.y, tanh2u(hadd2u(xv.y, q3.y)), accB[3]);
        }

        const int j   = j0 + lane;
        const int ib2 = i0 + iw;
        float sv[4];
        #pragma unroll
        for (int k = 0; k < 4; k++) {
            float2 fa = h22f2(accA[k]);
            float2 fb = h22f2(accB[k]);
            float d = (fa.x + fa.y) + (fb.x + fb.y);
            sv[k] = (j <= ib2 + k && j < T_DIM) ? fmaf(0.5f, d, hw0) : 0.0f;
        }

        sst[wid][lane] = make_float4(sv[0], sv[1], sv[2], sv[3]);
        __syncwarp();

        #pragma unroll 8
        for (int jj = 0; jj < 32; jj++) {
            float4 s4 = sst[wid][jj];       // broadcast LDS.128
            float2 vi = insp[jj][lane];     // LDS.64
            macc[0][0] += s4.x * vi.x; macc[0][1] += s4.x * vi.y;
            macc[1][0] += s4.y * vi.x; macc[1][1] += s4.y * vi.y;
            macc[2][0] += s4.z * vi.x; macc[2][1] += s4.z * vi.y;
            macc[3][0] += s4.w * vi.x; macc[3][1] += s4.w * vi.y;
        }
        __syncwarp();
    }

    #pragma unroll
    for (int k = 0; k < 4; k++) {
        int i = i0 + iw + k;
        if (i < T_DIM) {
            size_t o = (size_t)i * BH + b * 64;
            atomicAdd(&g_ma[o + lane],      macc[k][0]);
            atomicAdd(&g_ma[o + lane + 32], macc[k][1]);
        }
    }
}

// ============================================================================
// fused L1 + final (64-row tiles -> 200 blocks)
// ============================================================================
struct L1FArgs {
    const float* W[4];
    const float* B[4];
};

__global__ void __launch_bounds__(256) l1f_k(L1FArgs la, float* __restrict__ out)
{
    constexpr int ROWS = 64;
    __shared__ float Xa[64][ROWS + 4];
    __shared__ float Xb[64][ROWS + 4];
    __shared__ float Wa[64][32];
    __shared__ float Wb[64][32];
    __shared__ float Ba[32], Bb[32];

    const int tid = threadIdx.x;
    const int r0  = blockIdx.x * ROWS;
    const int tc  = tid & 7;
    const int tr  = tid >> 3;

    float pcv[2];
    float res[2][2];

    #pragma unroll
    for (int p = 0; p < 2; p++) {
        const float* Ta = g_t0 + (size_t)(2 * p)     * NROWS * 64;
        const float* Tb = g_t0 + (size_t)(2 * p + 1) * NROWS * 64;

        __syncthreads();
        for (int idx = tid; idx < ROWS * 16; idx += 256) {
            int r  = idx & 63;
            int k4 = (idx >> 6) << 2;
            float4 va = *(const float4*)&Ta[(size_t)(r0 + r) * 64 + k4];
            float4 vb = *(const float4*)&Tb[(size_t)(r0 + r) * 64 + k4];
            Xa[k4 + 0][r] = va.x; Xa[k4 + 1][r] = va.y;
            Xa[k4 + 2][r] = va.z; Xa[k4 + 3][r] = va.w;
            Xb[k4 + 0][r] = vb.x; Xb[k4 + 1][r] = vb.y;
            Xb[k4 + 2][r] = vb.z; Xb[k4 + 3][r] = vb.w;
        }
        for (int idx = tid; idx < 64 * 32; idx += 256) {
            Wa[idx >> 5][idx & 31] = la.W[2 * p][idx];
            Wb[idx >> 5][idx & 31] = la.W[2 * p + 1][idx];
        }
        if (tid < 32) { Ba[tid] = la.B[2 * p][tid]; Bb[tid] = la.B[2 * p + 1][tid]; }
        __syncthreads();

        float aa[2][4], ab[2][4];
        #pragma unroll
        for (int a = 0; a < 2; a++)
            #pragma unroll
            for (int c = 0; c < 4; c++) { aa[a][c] = 0.0f; ab[a][c] = 0.0f; }

        #pragma unroll 8
        for (int k = 0; k < 64; k++) {
            float2 xa = *(const float2*)&Xa[k][tr * 2];
            float2 xb = *(const float2*)&Xb[k][tr * 2];
            float4 wa = *(const float4*)&Wa[k][tc * 4];
            float4 wb = *(const float4*)&Wb[k][tc * 4];
            float xar[2] = {xa.x, xa.y};
            float xbr[2] = {xb.x, xb.y};
            float war[4] = {wa.x, wa.y, wa.z, wa.w};
            float wbr[4] = {wb.x, wb.y, wb.z, wb.w};
            #pragma unroll
            for (int a = 0; a < 2; a++)
                #pragma unroll
                for (int c = 0; c < 4; c++) {
                    aa[a][c] += xar[a] * war[c];
                    ab[a][c] += xbr[a] * wbr[c];
                }
        }

        #pragma unroll
        for (int a = 0; a < 2; a++) {
            float z = 0.0f;
            #pragma unroll
            for (int c = 0; c < 4; c++) {
                float va = leakyf(aa[a][c] + Ba[tc * 4 + c]);
                float vb = leakyf(ab[a][c] + Bb[tc * 4 + c]);
                z += va * vb;
            }
            #pragma unroll
            for (int off = 1; off < 8; off <<= 1)
                z += __shfl_xor_sync(0xffffffffu, z, off);
            res[p][a] = z;
        }
        if (p == 0) {
            #pragma unroll
            for (int a = 0; a < 2; a++) pcv[a] = sigf(res[0][a]);
        }
    }

    if (tc == 0) {
        #pragma unroll
        for (int a = 0; a < 2; a++) {
            int row = r0 + tr * 2 + a;
            float pc = pcv[a];
            float pv = sigf(res[1][a]) * pc;
            out[row]         = pc;
            out[NROWS + row] = pv;
        }
    }
}

// ============================================================================
extern "C" void kernel_launch(void* const* d_in, const int* in_sizes, int n_in,
                              void* d_out, int out_size)
{
    (void)in_sizes; (void)n_in; (void)out_size;
    const float* inp     = (const float*)d_in[0];
    const float* w1k     = (const float*)d_in[1];
    const float* w1b     = (const float*)d_in[2];
    const float* w2k     = (const float*)d_in[3];
    const float* w3k     = (const float*)d_in[4];
    const float* w0k     = (const float*)d_in[5];
    const float* pc_a0_k = (const float*)d_in[6],  *pc_a0_b = (const float*)d_in[7];
    const float* pc_b0_k = (const float*)d_in[8],  *pc_b0_b = (const float*)d_in[9];
    const float* pc_a1_k = (const float*)d_in[10], *pc_a1_b = (const float*)d_in[11];
    const float* pc_b1_k = (const float*)d_in[12], *pc_b1_b = (const float*)d_in[13];
    const float* pv_a0_k = (const float*)d_in[14], *pv_a0_b = (const float*)d_in[15];
    const float* pv_b0_k = (const float*)d_in[16], *pv_b0_b = (const float*)d_in[17];
    const float* pv_a1_k = (const float*)d_in[18], *pv_a1_b = (const float*)d_in[19];
    const float* pv_b1_k = (const float*)d_in[20], *pv_b1_b = (const float*)d_in[21];

    float *x1h, *y2, *y3, *ma, *t0;
    cudaGetSymbolAddress((void**)&x1h, g_x1h);
    cudaGetSymbolAddress((void**)&y2, g_y2);
    cudaGetSymbolAddress((void**)&y3, g_y3);
    cudaGetSymbolAddress((void**)&ma, g_ma);
    cudaGetSymbolAddress((void**)&t0, g_t0);

    // 1) x1 (-> half2, *0.5), y2, y3, + inp-only L0 towers (pc_b0, pv_b0)
    GemmBatch A = {};
    A.X[0] = inp; A.W[0] = w1k;     A.B[0] = w1b;     A.Y[0] = x1h;                          A.act[0] = 2;
    A.X[1] = inp; A.W[1] = w2k;     A.B[1] = nullptr; A.Y[1] = y2;                           A.act[1] = 0;
    A.X[2] = inp; A.W[2] = w3k;     A.B[2] = nullptr; A.Y[2] = y3;                           A.act[2] = 0;
    A.X[3] = inp; A.W[3] = pc_b0_k; A.B[3] = pc_b0_b; A.Y[3] = t0 + 1 * (size_t)NROWS * 64;  A.act[3] = 1;
    A.X[4] = inp; A.W[4] = pv_b0_k; A.B[4] = pv_b0_b; A.Y[4] = t0 + 3 * (size_t)NROWS * 64;  A.act[4] = 1;
    gemm64_k<<<dim3(NROWS / 64, 5), 256>>>(A);

    // 2) merged scan (also zeroes g_ma); emits q in half
    scan_k<<<BH / 32, 256>>>();

    // 3) scores + m_a (f16x2 tanh, tile-parallel, atomic accumulate)
    attn_k<<<dim3(16, B_DIM), 256>>>(inp, w0k);

    // 4) ma-based L0 towers
    GemmBatch L0 = {};
    L0.X[0] = ma; L0.W[0] = pc_a0_k; L0.B[0] = pc_a0_b; L0.Y[0] = t0 + 0 * (size_t)NROWS * 64; L0.act[0] = 1;
    L0.X[1] = ma; L0.W[1] = pv_a0_k; L0.B[1] = pv_a0_b; L0.Y[1] = t0 + 2 * (size_t)NROWS * 64; L0.act[1] = 1;
    gemm64_k<<<dim3(NROWS / 64, 2), 256>>>(L0);

    // 5) fused L1 + product-reduce + sigmoid
    L1FArgs la = {};
    la.W[0] = pc_a1_k; la.B[0] = pc_a1_b;
    la.W[1] = pc_b1_k; la.B[1] = pc_b1_b;
    la.W[2] = pv_a1_k; la.B[2] = pv_a1_b;
    la.W[3] = pv_b1_k; la.B[3] = pv_b1_b;
    l1f_k<<<NROWS / 64, 256>>>(la, (float*)d_out);
}

// round 11
// speedup vs baseline: 1.1286x; 1.0326x over previous
#include <cuda_runtime.h>
#include <cuda_fp16.h>

#define T_DIM 200
#define B_DIM 64
#define E_DIM 64
#define NROWS (T_DIM * B_DIM)   // 12800
#define BH (B_DIM * E_DIM)      // 4096
#define LOG2E 1.4426950408889634f

// ---- scratch ----
__device__ __half2 g_x1h[NROWS * 32];   // x1 pre-scaled by 0.5, half2 packed
__device__ float   g_y2[NROWS * E_DIM];
__device__ float   g_y3[NROWS * E_DIM];
__device__ __half  g_qh[NROWS * E_DIM]; // q pre-scaled by 0.5, half
__device__ float   g_ma[NROWS * E_DIM];

__constant__ int c_IBB[16] = {0,1,2,2,3,3,4,4,4,5,5,5,6,6,6,6};
__constant__ int c_JC [16] = {0,0,0,1,0,1,0,1,2,0,1,2,0,1,2,3};

__device__ __forceinline__ float ex2f(float x) {
    float r; asm("ex2.approx.f32 %0, %1;" : "=f"(r) : "f"(x)); return r;
}
__device__ __forceinline__ float rcpf(float x) {
    float r; asm("rcp.approx.f32 %0, %1;" : "=f"(r) : "f"(x)); return r;
}
__device__ __forceinline__ float sigf(float v) {
    return rcpf(1.0f + ex2f(-v * LOG2E));
}
__device__ __forceinline__ float leakyf(float v) {
    return (v >= 0.0f) ? v : 0.3f * v;
}
// ---- f16x2 helpers ----
__device__ __forceinline__ unsigned tanh2u(unsigned x) {
    unsigned r; asm("tanh.approx.f16x2 %0, %1;" : "=r"(r) : "r"(x)); return r;
}
__device__ __forceinline__ unsigned hadd2u(unsigned a, unsigned b) {
    unsigned r; asm("add.f16x2 %0, %1, %2;" : "=r"(r) : "r"(a), "r"(b)); return r;
}
__device__ __forceinline__ unsigned hfma2u(unsigned a, unsigned b, unsigned c) {
    unsigned r; asm("fma.rn.f16x2 %0, %1, %2, %3;" : "=r"(r) : "r"(a), "r"(b), "r"(c)); return r;
}
__device__ __forceinline__ unsigned f2h2(float hi, float lo) {
    unsigned r; asm("cvt.rn.f16x2.f32 %0, %1, %2;" : "=r"(r) : "f"(hi), "f"(lo)); return r;
}
__device__ __forceinline__ float2 h22f2(unsigned u) {
    float2 f;
    asm("{ .reg .f16 l, h; mov.b32 {l, h}, %2; cvt.f32.f16 %0, l; cvt.f32.f16 %1, h; }"
        : "=f"(f.x), "=f"(f.y) : "r"(u));
    return f;
}
// ---- f32x2 helpers ----
__device__ __forceinline__ unsigned long long pk2(float v) {
    unsigned long long r; asm("mov.b64 %0, {%1, %1};" : "=l"(r) : "f"(v)); return r;
}
__device__ __forceinline__ void ffma2(unsigned long long& d,
                                      unsigned long long a, unsigned long long b) {
    asm("fma.rn.f32x2 %0, %1, %2, %0;" : "+l"(d) : "l"(a), "l"(b));
}
__device__ __forceinline__ float2 up2(unsigned long long v) {
    float2 f; asm("mov.b64 {%0, %1}, %2;" : "=f"(f.x), "=f"(f.y) : "l"(v)); return f;
}

// ============================================================================
// GEMM (HOUT=64), up to 3 towers, f32x2 inner, 64-row tiles.
// act: 0=none, 2 = *0.5 then convert to half2 (Y is __half2*)
// ============================================================================
struct GemmBatch {
    const float* X[3];
    const float* W[3];
    const float* B[3];
    float*       Y[3];
    int          act[3];
};

__global__ void __launch_bounds__(256) gemm64_k(GemmBatch gb)
{
    constexpr int ROWS = 64;
    __shared__ __align__(16) float Xt[64][ROWS + 4];
    __shared__ __align__(16) float Ws[64][64];
    __shared__ float Bs[64];

    const int tw = blockIdx.y;
    const float* __restrict__ X  = gb.X[tw];
    const float* __restrict__ W  = gb.W[tw];
    const float* __restrict__ Bp = gb.B[tw];
    float* __restrict__ Y        = gb.Y[tw];
    const int act = gb.act[tw];

    const int tid = threadIdx.x;
    const int r0  = blockIdx.x * ROWS;

    for (int idx = tid; idx < 1024; idx += 256)
        *(((float4*)Ws) + idx) = ((const float4*)W)[idx];
    if (tid < 64) Bs[tid] = Bp ? Bp[tid] : 0.0f;
    for (int idx = tid; idx < ROWS * 16; idx += 256) {
        int r  = idx & 63;
        int k4 = (idx >> 6) << 2;
        float4 v = *(const float4*)&X[(size_t)(r0 + r) * 64 + k4];
        Xt[k4 + 0][r] = v.x; Xt[k4 + 1][r] = v.y;
        Xt[k4 + 2][r] = v.z; Xt[k4 + 3][r] = v.w;
    }
    __syncthreads();

    const int tc = tid & 15;
    const int tr = tid >> 4;
    unsigned long long acc[2][4];
    #pragma unroll
    for (int p = 0; p < 2; p++)
        #pragma unroll
        for (int c = 0; c < 4; c++) acc[p][c] = 0ull;

    #pragma unroll 8
    for (int k = 0; k < 64; k++) {
        ulonglong2 X0 = *(const ulonglong2*)&Xt[k][tr * 4];
        float4 wv = *(const float4*)&Ws[k][tc * 4];
        unsigned long long wp[4] = {pk2(wv.x), pk2(wv.y), pk2(wv.z), pk2(wv.w)};
        #pragma unroll
        for (int c = 0; c < 4; c++) {
            ffma2(acc[0][c], X0.x, wp[c]);
            ffma2(acc[1][c], X0.y, wp[c]);
        }
    }

    #pragma unroll
    for (int p = 0; p < 2; p++) {
        float r0c[4], r1c[4];
        #pragma unroll
        for (int c = 0; c < 4; c++) {
            float2 f = up2(acc[p][c]);
            r0c[c] = f.x + Bs[tc * 4 + c];
            r1c[c] = f.y + Bs[tc * 4 + c];
        }
        int rowa = r0 + tr * 4 + 2 * p;
        if (act == 2) {
            __half2* Yh = (__half2*)Y;
            uint2 o0, o1;
            o0.x = f2h2(r0c[1] * 0.5f, r0c[0] * 0.5f);
            o0.y = f2h2(r0c[3] * 0.5f, r0c[2] * 0.5f);
            o1.x = f2h2(r1c[1] * 0.5f, r1c[0] * 0.5f);
            o1.y = f2h2(r1c[3] * 0.5f, r1c[2] * 0.5f);
            *(uint2*)&Yh[(size_t)rowa * 32 + tc * 2]       = o0;
            *(uint2*)&Yh[(size_t)(rowa + 1) * 32 + tc * 2] = o1;
        } else {
            float4 o0 = make_float4(r0c[0], r0c[1], r0c[2], r0c[3]);
            float4 o1 = make_float4(r1c[0], r1c[1], r1c[2], r1c[3]);
            *(float4*)&Y[(size_t)rowa * 64 + tc * 4]       = o0;
            *(float4*)&Y[(size_t)(rowa + 1) * 64 + tc * 4] = o1;
        }
    }
}

// ============================================================================
// merged scan (+ zero g_ma): 128 blocks x 256 thr. Block = 32 columns.
// ============================================================================
__global__ void __launch_bounds__(256) scan_k()
{
    __shared__ float parts[8][32];

    const int tid  = blockIdx.x * 256 + threadIdx.x;
    {
        float4 z4 = make_float4(0.f, 0.f, 0.f, 0.f);
        float4* mz = (float4*)g_ma;
        for (int i = tid; i < NROWS * 16; i += 32768) mz[i] = z4;
    }

    const int lane = threadIdx.x & 31;
    const int w    = threadIdx.x >> 5;
    const int col  = blockIdx.x * 32 + lane;
    const int t0   = w * 25;

    float s = 0.0f;
    #pragma unroll
    for (int t = 0; t < 25; t++)
        s += g_y3[(size_t)(t0 + t) * BH + col];
    parts[w][lane] = s;
    __syncthreads();

    float acc = 0.0f;
    #pragma unroll
    for (int p = 0; p < 7; p++) {
        float v = parts[p][lane];
        if (p < w) acc += v;
    }

    #pragma unroll
    for (int t = 0; t < 25; t++) {
        size_t o = (size_t)(t0 + t) * BH + col;
        acc += g_y3[o];
        float invt = __fdividef(1.0f, (float)(t0 + t + 1));
        g_qh[o] = __float2half((g_y2[o] + acc * invt) * 0.5f);
    }
}

// ============================================================================
// attention (unchanged from R8/R10): grid (16, 64).
// ============================================================================
__global__ void __launch_bounds__(256) attn_k(const float* __restrict__ inp,
                                              const float* __restrict__ w0)
{
    __shared__ __align__(16) unsigned x1s[32 * 34];
    __shared__ __align__(16) unsigned qhs[32 * 34];
    __shared__ __align__(16) float2   insp[32][34];
    __shared__ __align__(16) unsigned w0h[32];
    __shared__ __align__(16) float    w0f[64];
    __shared__ __align__(16) float4   sst[8][32];

    const int b    = blockIdx.y;
    const int ibb  = c_IBB[blockIdx.x];
    const int jc   = c_JC[blockIdx.x];
    const int i0   = ibb * 32;
    const int tid  = threadIdx.x;
    const int wid  = tid >> 5;
    const int lane = tid & 31;
    const int iw   = wid << 2;

    if (tid < 64) w0f[tid] = w0[tid];
    if (tid >= 64 && tid < 96) {
        int t = tid - 64;
        w0h[t] = f2h2(w0[2 * t + 1], w0[2 * t]);
    }
    {
        int r = tid >> 3, c = tid & 7;
        int ii = i0 + r;
        uint4 v = make_uint4(0u, 0u, 0u, 0u);
        if (ii < T_DIM)
            v = *(const uint4*)&g_qh[(size_t)ii * BH + b * 64 + c * 8];
        unsigned* dst = &qhs[r * 34 + c * 4];
        *(uint2*)dst       = make_uint2(v.x, v.y);
        *(uint2*)(dst + 2) = make_uint2(v.z, v.w);
    }
    __syncthreads();

    float hw0 = 0.0f;
    #pragma unroll 16
    for (int h = 0; h < 64; h++) hw0 += w0f[h];
    hw0 *= 0.5f;

    float macc[4][2];
    #pragma unroll
    for (int k = 0; k < 4; k++) { macc[k][0] = 0.0f; macc[k][1] = 0.0f; }

    const int ntiles = (2 * jc + 1 <= ibb) ? 2 : 1;

    for (int t = 0; t < ntiles; t++) {
        const int j0 = (2 * jc + t) * 32;
        if (t) __syncthreads();
        {
            int jj = tid >> 3, c = tid & 7;
            int j = j0 + jj;
            uint4 v = make_uint4(0u, 0u, 0u, 0u);
            if (j < T_DIM)
                v = *(const uint4*)&g_x1h[((size_t)j * B_DIM + b) * 32 + c * 4];
            unsigned* dst = &x1s[jj * 34 + c * 4];
            *(uint2*)dst       = make_uint2(v.x, v.y);
            *(uint2*)(dst + 2) = make_uint2(v.z, v.w);
        }
        {
            int jj = tid >> 3;
            int h4 = (tid & 7) << 2;
            int j = j0 + jj;
            float4 z4 = make_float4(0.f, 0.f, 0.f, 0.f);
            float4 ia = z4, ib = z4;
            if (j < T_DIM) {
                const float* pi = &inp[(size_t)j * BH + b * 64];
                ia = *(const float4*)(pi + h4);
                ib = *(const float4*)(pi + h4 + 32);
            }
            *(float4*)&insp[jj][h4]     = make_float4(ia.x, ib.x, ia.y, ib.y);
            *(float4*)&insp[jj][h4 + 2] = make_float4(ia.z, ib.z, ia.w, ib.w);
        }
        __syncthreads();

        unsigned accA[4], accB[4];
        #pragma unroll
        for (int k = 0; k < 4; k++) { accA[k] = 0u; accB[k] = 0u; }

        const unsigned* xrow = &x1s[lane * 34];
        const unsigned* q0r  = &qhs[(iw + 0) * 34];
        const unsigned* q1r  = &qhs[(iw + 1) * 34];
        const unsigned* q2r  = &qhs[(iw + 2) * 34];
        const unsigned* q3r  = &qhs[(iw + 3) * 34];

        #pragma unroll
        for (int p = 0; p < 16; p++) {
            uint2 xv = *(const uint2*)&xrow[2 * p];
            uint2 wv = *(const uint2*)&w0h[2 * p];
            uint2 q0 = *(const uint2*)&q0r[2 * p];
            uint2 q1 = *(const uint2*)&q1r[2 * p];
            uint2 q2 = *(const uint2*)&q2r[2 * p];
            uint2 q3 = *(const uint2*)&q3r[2 * p];
            accA[0] = hfma2u(wv.x, tanh2u(hadd2u(xv.x, q0.x)), accA[0]);
            accA[1] = hfma2u(wv.x, tanh2u(hadd2u(xv.x, q1.x)), accA[1]);
            accA[2] = hfma2u(wv.x, tanh2u(hadd2u(xv.x, q2.x)), accA[2]);
            accA[3] = hfma2u(wv.x, tanh2u(hadd2u(xv.x, q3.x)), accA[3]);
            accB[0] = hfma2u(wv.y, tanh2u(hadd2u(xv.y, q0.y)), accB[0]);
            accB[1] = hfma2u(wv.y, tanh2u(hadd2u(xv.y, q1.y)), accB[1]);
            accB[2] = hfma2u(wv.y, tanh2u(hadd2u(xv.y, q2.y)), accB[2]);
            accB[3] = hfma2u(wv.y, tanh2u(hadd2u(xv.y, q3.y)), accB[3]);
        }

        const int j   = j0 + lane;
        const int ib2 = i0 + iw;
        float sv[4];
        #pragma unroll
        for (int k = 0; k < 4; k++) {
            float2 fa = h22f2(accA[k]);
            float2 fb = h22f2(accB[k]);
            float d = (fa.x + fa.y) + (fb.x + fb.y);
            sv[k] = (j <= ib2 + k && j < T_DIM) ? fmaf(0.5f, d, hw0) : 0.0f;
        }

        sst[wid][lane] = make_float4(sv[0], sv[1], sv[2], sv[3]);
        __syncwarp();

        #pragma unroll 8
        for (int jj = 0; jj < 32; jj++) {
            float4 s4 = sst[wid][jj];
            float2 vi = insp[jj][lane];
            macc[0][0] += s4.x * vi.x; macc[0][1] += s4.x * vi.y;
            macc[1][0] += s4.y * vi.x; macc[1][1] += s4.y * vi.y;
            macc[2][0] += s4.z * vi.x; macc[2][1] += s4.z * vi.y;
            macc[3][0] += s4.w * vi.x; macc[3][1] += s4.w * vi.y;
        }
        __syncwarp();
    }

    #pragma unroll
    for (int k = 0; k < 4; k++) {
        int i = i0 + iw + k;
        if (i < T_DIM) {
            size_t o = (size_t)i * BH + b * 64;
            atomicAdd(&g_ma[o + lane],      macc[k][0]);
            atomicAdd(&g_ma[o + lane + 32], macc[k][1]);
        }
    }
}

// ============================================================================
// fused tail: for each pass p in {pc, pv}:
//   side a: ma  -> L0 (64, leaky) -> L1 (32, leaky)  [kept in regs]
//   side b: inp -> L0 (64, leaky) -> L1 (32, leaky)
//   dot over 32, sigmoid; pv *= pc.  200 blocks x 64 rows, 256 thr.
// ============================================================================
struct TailArgs {
    const float* W0[4]; const float* B0[4];   // pc_a, pc_b, pv_a, pv_b
    const float* W1[4]; const float* B1[4];
};

__global__ void __launch_bounds__(256) tail_k(TailArgs ta,
                                              const float* __restrict__ inp,
                                              float* __restrict__ out)
{
    __shared__ __align__(16) float XT[64][68];   // k-major input tile
    __shared__ __align__(16) float H0[64][68];   // row-major hidden
    __shared__ __align__(16) float W0s[64][64];
    __shared__ __align__(16) float W1s[64][32];
    __shared__ float B0s[64], B1s[32];

    const int tid = threadIdx.x;
    const int r0  = blockIdx.x * 64;
    // L0 thread mapping
    const int tc  = tid & 15;      // 16 col-groups * 4 cols
    const int tr  = tid >> 4;      // 16 row-groups * 4 rows
    // L1 thread mapping
    const int tc2 = tid & 7;       // 8 col-groups * 4 cols
    const int tr2 = tid >> 3;      // 32 row-groups * 2 rows

    float zres[2][2];              // [pass][row]

    #pragma unroll
    for (int p = 0; p < 2; p++) {
        float zA[2][4];
        #pragma unroll
        for (int side = 0; side < 2; side++) {
            const int tw = p * 2 + side;
            const float* Xsrc = (side == 0) ? g_ma : inp;

            __syncthreads();   // previous stage's smem reads done
            // load XT (transposed), W0, W1, biases
            for (int idx = tid; idx < 64 * 16; idx += 256) {
                int r  = idx & 63;
                int k4 = (idx >> 6) << 2;
                float4 v = *(const float4*)&Xsrc[(size_t)(r0 + r) * 64 + k4];
                XT[k4 + 0][r] = v.x; XT[k4 + 1][r] = v.y;
                XT[k4 + 2][r] = v.z; XT[k4 + 3][r] = v.w;
            }
            for (int idx = tid; idx < 1024; idx += 256)
                ((float4*)W0s)[idx] = ((const float4*)ta.W0[tw])[idx];
            for (int idx = tid; idx < 512; idx += 256)
                ((float4*)W1s)[idx] = ((const float4*)ta.W1[tw])[idx];
            if (tid < 64) B0s[tid] = ta.B0[tw][tid];
            if (tid < 32) B1s[tid] = ta.B1[tw][tid];
            __syncthreads();

            // ---- L0: H0[r][c] = leaky(sum_k XT[k][r] * W0s[k][c] + b) ----
            unsigned long long acc[2][4];
            #pragma unroll
            for (int q = 0; q < 2; q++)
                #pragma unroll
                for (int c = 0; c < 4; c++) acc[q][c] = 0ull;

            #pragma unroll 8
            for (int k = 0; k < 64; k++) {
                ulonglong2 X0 = *(const ulonglong2*)&XT[k][tr * 4];
                float4 wv = *(const float4*)&W0s[k][tc * 4];
                unsigned long long wp[4] = {pk2(wv.x), pk2(wv.y), pk2(wv.z), pk2(wv.w)};
                #pragma unroll
                for (int c = 0; c < 4; c++) {
                    ffma2(acc[0][c], X0.x, wp[c]);
                    ffma2(acc[1][c], X0.y, wp[c]);
                }
            }
            #pragma unroll
            for (int q = 0; q < 2; q++) {
                float ra[4], rb[4];
                #pragma unroll
                for (int c = 0; c < 4; c++) {
                    float2 f = up2(acc[q][c]);
                    ra[c] = leakyf(f.x + B0s[tc * 4 + c]);
                    rb[c] = leakyf(f.y + B0s[tc * 4 + c]);
                }
                int rr = tr * 4 + 2 * q;
                *(float4*)&H0[rr][tc * 4]     = make_float4(ra[0], ra[1], ra[2], ra[3]);
                *(float4*)&H0[rr + 1][tc * 4] = make_float4(rb[0], rb[1], rb[2], rb[3]);
            }
            __syncthreads();

            // ---- L1: zB[a][c] = leaky(sum_k H0[2*tr2+a][k] * W1s[k][tc2*4+c] + b) ----
            float bb[2][4];
            #pragma unroll
            for (int a = 0; a < 2; a++)
                #pragma unroll
                for (int c = 0; c < 4; c++) bb[a][c] = 0.0f;

            #pragma unroll 8
            for (int k = 0; k < 64; k++) {
                float x0 = H0[2 * tr2][k];
                float x1 = H0[2 * tr2 + 1][k];
                float4 wv = *(const float4*)&W1s[k][tc2 * 4];
                bb[0][0] += x0 * wv.x; bb[0][1] += x0 * wv.y;
                bb[0][2] += x0 * wv.z; bb[0][3] += x0 * wv.w;
                bb[1][0] += x1 * wv.x; bb[1][1] += x1 * wv.y;
                bb[1][2] += x1 * wv.z; bb[1][3] += x1 * wv.w;
            }

            if (side == 0) {
                #pragma unroll
                for (int a = 0; a < 2; a++)
                    #pragma unroll
                    for (int c = 0; c < 4; c++)
                        zA[a][c] = leakyf(bb[a][c] + B1s[tc2 * 4 + c]);
            } else {
                #pragma unroll
                for (int a = 0; a < 2; a++) {
                    float z = 0.0f;
                    #pragma unroll
                    for (int c = 0; c < 4; c++)
                        z += zA[a][c] * leakyf(bb[a][c] + B1s[tc2 * 4 + c]);
                    z += __shfl_xor_sync(0xffffffffu, z, 1);
                    z += __shfl_xor_sync(0xffffffffu, z, 2);
                    z += __shfl_xor_sync(0xffffffffu, z, 4);
                    zres[p][a] = z;
                }
            }
        }
    }

    if (tc2 == 0) {
        #pragma unroll
        for (int a = 0; a < 2; a++) {
            int row = r0 + tr2 * 2 + a;
            float pc = sigf(zres[0][a]);
            float pv = sigf(zres[1][a]) * pc;
            out[row]         = pc;
            out[NROWS + row] = pv;
        }
    }
}

// ============================================================================
extern "C" void kernel_launch(void* const* d_in, const int* in_sizes, int n_in,
                              void* d_out, int out_size)
{
    (void)in_sizes; (void)n_in; (void)out_size;
    const float* inp     = (const float*)d_in[0];
    const float* w1k     = (const float*)d_in[1];
    const float* w1b     = (const float*)d_in[2];
    const float* w2k     = (const float*)d_in[3];
    const float* w3k     = (const float*)d_in[4];
    const float* w0k     = (const float*)d_in[5];
    const float* pc_a0_k = (const float*)d_in[6],  *pc_a0_b = (const float*)d_in[7];
    const float* pc_b0_k = (const float*)d_in[8],  *pc_b0_b = (const float*)d_in[9];
    const float* pc_a1_k = (const float*)d_in[10], *pc_a1_b = (const float*)d_in[11];
    const float* pc_b1_k = (const float*)d_in[12], *pc_b1_b = (const float*)d_in[13];
    const float* pv_a0_k = (const float*)d_in[14], *pv_a0_b = (const float*)d_in[15];
    const float* pv_b0_k = (const float*)d_in[16], *pv_b0_b = (const float*)d_in[17];
    const float* pv_a1_k = (const float*)d_in[18], *pv_a1_b = (const float*)d_in[19];
    const float* pv_b1_k = (const float*)d_in[20], *pv_b1_b = (const float*)d_in[21];

    float *x1h, *y2, *y3;
    cudaGetSymbolAddress((void**)&x1h, g_x1h);
    cudaGetSymbolAddress((void**)&y2, g_y2);
    cudaGetSymbolAddress((void**)&y3, g_y3);

    // 1) x1 (-> half2, *0.5), y2, y3
    GemmBatch A = {};
    A.X[0] = inp; A.W[0] = w1k; A.B[0] = w1b;     A.Y[0] = x1h; A.act[0] = 2;
    A.X[1] = inp; A.W[1] = w2k; A.B[1] = nullptr; A.Y[1] = y2;  A.act[1] = 0;
    A.X[2] = inp; A.W[2] = w3k; A.B[2] = nullptr; A.Y[2] = y3;  A.act[2] = 0;
    gemm64_k<<<dim3(NROWS / 64, 3), 256>>>(A);

    // 2) merged scan (also zeroes g_ma); emits q in half
    scan_k<<<BH / 32, 256>>>();

    // 3) scores + m_a (f16x2 tanh, tile-parallel, atomic accumulate)
    attn_k<<<dim3(16, B_DIM), 256>>>(inp, w0k);

    // 4) fused tail: all 4 towers, 2 layers each, dot + sigmoid -> out
    TailArgs ta = {};
    ta.W0[0] = pc_a0_k; ta.B0[0] = pc_a0_b; ta.W1[0] = pc_a1_k; ta.B1[0] = pc_a1_b;
    ta.W0[1] = pc_b0_k; ta.B0[1] = pc_b0_b; ta.W1[1] = pc_b1_k; ta.B1[1] = pc_b1_b;
    ta.W0[2] = pv_a0_k; ta.B0[2] = pv_a0_b; ta.W1[2] = pv_a1_k; ta.B1[2] = pv_a1_b;
    ta.W0[3] = pv_b0_k; ta.B0[3] = pv_b0_b; ta.W1[3] = pv_b1_k; ta.B1[3] = pv_b1_b;
    tail_k<<<NROWS / 64, 256>>>(ta, inp, (float*)d_out);
}